// round 1
// baseline (speedup 1.0000x reference)
#include <cuda_runtime.h>
#include <cstring>

#define Bb 8
#define Hh 8
#define Nq 1024
#define Cc 256
#define HD 64
#define BH (Bb*Hh)

// ---------------- scratch (device globals; no allocation allowed) ----------
__device__ float g_Qb[BH*Nq*HD];   // [b][h][n][d]  16MB
__device__ float g_Kb[BH*Nq*HD];   // [b][h][n][d]  16MB
__device__ float g_red_s[128];
__device__ float g_red_q[128];
__device__ float g_bnp[2][Hh][2];  // [tensor][head][{scale,shift}]

// ---------------- f32x2 helpers --------------------------------------------
__device__ __forceinline__ unsigned long long splat_f32(float x){
    unsigned long long r;
    asm("mov.b64 %0, {%1, %1};" : "=l"(r) : "f"(x));
    return r;
}
__device__ __forceinline__ void ffma2(unsigned long long &d,
                                      unsigned long long a,
                                      unsigned long long b){
    asm("fma.rn.f32x2 %0, %1, %2, %0;" : "+l"(d) : "l"(a), "l"(b));
}
__device__ __forceinline__ float2 unpack2(unsigned long long v){
    float2 r;
    asm("mov.b64 {%0, %1}, %2;" : "=f"(r.x), "=f"(r.y) : "l"(v));
    return r;
}

// ---------------- 1) projection GEMM  q,k = x @ W^T ------------------------
// C[m, col] = sum_c x[m,c] * W[col,c];  cols 0..511 -> Q, 512..1023 -> K.
// Output written directly in [b][h][n][d] layout.
__global__ __launch_bounds__(256) void proj_kernel(const float* __restrict__ x,
                                                   const float* __restrict__ qw,
                                                   const float* __restrict__ kw){
    __shared__ float Ast[16][68];
    __shared__ float Bst[16][68];
    const int tid = threadIdx.x;
    const int tx = tid & 15, ty = tid >> 4;
    const int bm = blockIdx.y * 64;
    const int cb = blockIdx.x;            // 0..15 (64-col slab == one head chunk)
    const float* Wp = (cb < 8) ? (qw + (size_t)cb*64*Cc) : (kw + (size_t)(cb-8)*64*Cc);
    float* outbuf = (cb < 8) ? g_Qb : g_Kb;
    const int hsel = cb & 7;

    unsigned long long acc[4][2];
    #pragma unroll
    for (int i=0;i<4;i++){ acc[i][0]=0ull; acc[i][1]=0ull; }

    const int row_ld = tid >> 2;          // 0..63
    const int kq = tid & 3;               // 0..3

    for (int kc = 0; kc < 16; kc++){
        const int k0 = kc*16;
        float4 a4 = *reinterpret_cast<const float4*>(x  + (size_t)(bm + row_ld)*Cc + k0 + kq*4);
        float4 b4 = *reinterpret_cast<const float4*>(Wp + (size_t)row_ld*Cc        + k0 + kq*4);
        Ast[kq*4+0][row_ld]=a4.x; Ast[kq*4+1][row_ld]=a4.y;
        Ast[kq*4+2][row_ld]=a4.z; Ast[kq*4+3][row_ld]=a4.w;
        Bst[kq*4+0][row_ld]=b4.x; Bst[kq*4+1][row_ld]=b4.y;
        Bst[kq*4+2][row_ld]=b4.z; Bst[kq*4+3][row_ld]=b4.w;
        __syncthreads();
        #pragma unroll
        for (int k=0;k<16;k++){
            float4 av = *reinterpret_cast<const float4*>(&Ast[k][ty*4]);
            const unsigned long long* bpp =
                reinterpret_cast<const unsigned long long*>(&Bst[k][tx*4]);
            unsigned long long bp0 = bpp[0], bp1 = bpp[1];
            float avv[4] = {av.x, av.y, av.z, av.w};
            #pragma unroll
            for (int i=0;i<4;i++){
                unsigned long long ap = splat_f32(avv[i]);
                ffma2(acc[i][0], ap, bp0);
                ffma2(acc[i][1], ap, bp1);
            }
        }
        __syncthreads();
    }
    #pragma unroll
    for (int i=0;i<4;i++){
        const int m = bm + ty*4 + i;
        const int b = m >> 10, n = m & 1023;
        float2 p0 = unpack2(acc[i][0]);
        float2 p1 = unpack2(acc[i][1]);
        float4 o = make_float4(p0.x, p0.y, p1.x, p1.y);
        float* dst = outbuf + (((size_t)(b*Hh + hsel))*Nq + n)*HD + tx*4;
        *reinterpret_cast<float4*>(dst) = o;
    }
}

// ---------------- 2) BN stats: per (tensor, b, h) partial sums -------------
__global__ __launch_bounds__(256) void stats_kernel(){
    __shared__ float ss[256], sq[256];
    const int t = blockIdx.x >> 6;
    const int idx = blockIdx.x & 63;                  // b*8 + h
    const float* base = (t ? g_Kb : g_Qb) + (size_t)idx * 65536;
    const float4* b4p = reinterpret_cast<const float4*>(base);
    float s = 0.f, q = 0.f;
    for (int i = threadIdx.x; i < 16384; i += 256){
        float4 v = b4p[i];
        s += (v.x + v.y) + (v.z + v.w);
        q += v.x*v.x + v.y*v.y + v.z*v.z + v.w*v.w;
    }
    ss[threadIdx.x] = s; sq[threadIdx.x] = q;
    __syncthreads();
    for (int o = 128; o > 0; o >>= 1){
        if (threadIdx.x < o){
            ss[threadIdx.x] += ss[threadIdx.x+o];
            sq[threadIdx.x] += sq[threadIdx.x+o];
        }
        __syncthreads();
    }
    if (threadIdx.x == 0){ g_red_s[blockIdx.x] = ss[0]; g_red_q[blockIdx.x] = sq[0]; }
}

__global__ void bn_finalize_kernel(const float* __restrict__ bnw,
                                   const float* __restrict__ bnb){
    const int tid = threadIdx.x;
    if (tid < 16){
        const int t = tid >> 3, h = tid & 7;
        float S = 0.f, Q = 0.f;
        for (int b = 0; b < 8; b++){
            const int j = t*64 + b*8 + h;
            S += g_red_s[j]; Q += g_red_q[j];
        }
        const float inv = 1.0f / 524288.0f;
        const float mean = S * inv;
        const float var  = Q * inv - mean*mean;
        const float sc = bnw[h] * rsqrtf(var + 1e-5f);
        const float sh = bnb[h] - mean * sc;
        g_bnp[t][h][0] = sc; g_bnp[t][h][1] = sh;
    }
}

// ---------------- 3) BN affine + L2 normalize (in place) -------------------
// K additionally scaled by 1/16 (= 1/sqrt(256) score scale).
__global__ __launch_bounds__(256) void norm_kernel(){
    const int tid = threadIdx.x;
    const int w = tid >> 5, l = tid & 31;
    const int row = blockIdx.x*8 + w;             // 0..131071
    const int t  = row >> 16;
    const int r2 = row & 65535;                   // (b*8+h)*1024 + n
    const int h  = (r2 >> 10) & 7;
    float* base = (t ? g_Kb : g_Qb) + (size_t)r2 * 64;
    float2 v = reinterpret_cast<float2*>(base)[l];
    const float sc = g_bnp[t][h][0], sf = g_bnp[t][h][1];
    v.x = fmaf(v.x, sc, sf);
    v.y = fmaf(v.y, sc, sf);
    float ssum = v.x*v.x + v.y*v.y;
    #pragma unroll
    for (int o = 16; o > 0; o >>= 1) ssum += __shfl_xor_sync(0xffffffffu, ssum, o);
    float nrm = fmaxf(sqrtf(ssum), 1e-12f);
    const float r = (t ? 0.0625f : 1.0f) / nrm;
    v.x *= r; v.y *= r;
    reinterpret_cast<float2*>(base)[l] = v;
}

// ---------------- 4) fused scores GEMM + sparsemax(axis=n) + store ---------
// Block = (m-tile of 32, bh). Thread (w,l): column m = l, rows n = ch*128 +
// jl*32 + 2w + {0,1}; 64 scores/thread held as 32 f32x2 accumulators.
__global__ __launch_bounds__(512, 1) void attn_kernel(float* __restrict__ out){
    __shared__ float Kst[64][33];     // [d][m]
    __shared__ float Qst[64][130];    // [d][n_local], pad keeps 8B alignment
    __shared__ float red_s[16][32];
    __shared__ float red_c[16][32];
    __shared__ float taus[32];
    __shared__ int   sh_flag;

    const int tid = threadIdx.x;
    const int w = tid >> 5, l = tid & 31;
    const int bh = blockIdx.y;
    const int m0 = blockIdx.x * 32;
    const float* Kbase = g_Kb + (size_t)bh * Nq * 64;
    const float* Qbase = g_Qb + (size_t)bh * Nq * 64;

    // K tile, transposed
    {
        const int mk = tid >> 4;          // 0..31
        const int dg = tid & 15;
        float4 kv = *reinterpret_cast<const float4*>(Kbase + (size_t)(m0 + mk)*64 + dg*4);
        Kst[dg*4+0][mk]=kv.x; Kst[dg*4+1][mk]=kv.y;
        Kst[dg*4+2][mk]=kv.z; Kst[dg*4+3][mk]=kv.w;
    }

    unsigned long long acc[32];
    #pragma unroll
    for (int i=0;i<32;i++) acc[i]=0ull;

    const int nr0 = 2*w;

    #pragma unroll
    for (int ch = 0; ch < 8; ch++){
        __syncthreads();
        #pragma unroll
        for (int it = 0; it < 4; it++){
            const int task = tid + it*512;
            const int nr = task >> 4;     // 0..127
            const int dg = task & 15;
            float4 qv = *reinterpret_cast<const float4*>(
                Qbase + (size_t)(ch*128 + nr)*64 + dg*4);
            Qst[dg*4+0][nr]=qv.x; Qst[dg*4+1][nr]=qv.y;
            Qst[dg*4+2][nr]=qv.z; Qst[dg*4+3][nr]=qv.w;
        }
        __syncthreads();
        #pragma unroll 4
        for (int d = 0; d < 64; d++){
            unsigned long long kp = splat_f32(Kst[d][l]);
            #pragma unroll
            for (int jl = 0; jl < 4; jl++){
                unsigned long long qp = *reinterpret_cast<const unsigned long long*>(
                    &Qst[d][jl*32 + nr0]);
                ffma2(acc[ch*4+jl], qp, kp);
            }
        }
    }

    float z[64];
    #pragma unroll
    for (int i=0;i<32;i++){
        float2 p = unpack2(acc[i]);
        z[2*i] = p.x; z[2*i+1] = p.y;
    }

    // Michelot fixed point for sparsemax tau over the 1024-row column m=l.
    float tau = -1.0f;   // all z in [-1/16, 1/16] => first iter = full sum init
    for (int iter = 0; iter < 48; iter++){
        float s = 0.f, c = 0.f;
        #pragma unroll
        for (int i=0;i<64;i++){
            if (z[i] > tau){ s += z[i]; c += 1.0f; }
        }
        red_s[w][l] = s; red_c[w][l] = c;
        __syncthreads();
        if (w == 0){
            float S = 0.f, Ccnt = 0.f;
            #pragma unroll
            for (int ww=0; ww<16; ww++){ S += red_s[ww][l]; Ccnt += red_c[ww][l]; }
            float nt = (Ccnt > 0.f) ? (S - 1.0f)/Ccnt : tau;
            unsigned bal = __ballot_sync(0xffffffffu, nt != tau);
            taus[l] = nt;
            if (l == 0) sh_flag = (bal != 0u);
        }
        __syncthreads();
        tau = taus[l];
        if (!sh_flag) break;
    }

    // out[b][n][h*1024 + m]
    const int b = bh >> 3, h = bh & 7;
    const size_t obase = ((size_t)b * Nq) * 8192 + (size_t)h * 1024 + m0 + l;
    #pragma unroll
    for (int idx = 0; idx < 32; idx++){
        const int ch = idx >> 2, jl = idx & 3;
        const int n = ch*128 + jl*32 + nr0;
        float v0 = z[2*idx]   - tau;
        float v1 = z[2*idx+1] - tau;
        out[obase + (size_t)n*8192]       = v0 > 0.f ? v0 : 0.f;
        out[obase + (size_t)(n+1)*8192]   = v1 > 0.f ? v1 : 0.f;
    }
}

// ---------------- launcher --------------------------------------------------
extern "C" void kernel_launch(void* const* d_in, const int* in_sizes, int n_in,
                              void* d_out, int out_size){
    const float* x   = (const float*)d_in[0];
    const float* qw  = (const float*)d_in[1];
    const float* kw  = (const float*)d_in[2];
    const float* bnw = (const float*)d_in[3];
    const float* bnb = (const float*)d_in[4];
    float* out = (float*)d_out;
    (void)in_sizes; (void)n_in; (void)out_size;

    proj_kernel<<<dim3(16, 128), 256>>>(x, qw, kw);
    stats_kernel<<<128, 256>>>();
    bn_finalize_kernel<<<1, 32>>>(bnw, bnb);
    norm_kernel<<<16384, 256>>>();
    attn_kernel<<<dim3(32, 64), 512>>>(out);
}